// round 7
// baseline (speedup 1.0000x reference)
#include <cuda_runtime.h>
#include <string.h>

// Per-channel 5x5 correlation, stride=1, pad=2; 128 planes of 512x512 f32.
// Register-rolling, 4 warps/CTA, warp owns a 256-wide x 16-row strip.
//   - lane owns 8 x; loads its own halo: LDG.64(x0-2) + 2x LDG.128 + LDG.64(x0+8).
//   - depth-2 row prefetch (double-buffered raw regs, parity compile-time).
//   - 5 pending output rows in registers, mod-5 rotation; slot's first tap is
//     mul.f32x2; completed row stored straight from acc (bit-cast, no staging).
//   - f32x2 packing via memcpy bit-cast so ptxas can alias the 6 even pairs
//     onto the vector-load registers (no forced MOVs).

#define IMG  512
#define R    16
#define NSTEP (R + 4)      // 20 input rows per strip

typedef unsigned long long u64;

__device__ __forceinline__ u64 pk(float lo, float hi) {
    float2 t; t.x = lo; t.y = hi;
    u64 r; memcpy(&r, &t, 8);
    return r;
}
__device__ __forceinline__ u64 pk2(float2 t) {
    u64 r; memcpy(&r, &t, 8);
    return r;
}
__device__ __forceinline__ u64 fma2(u64 a, u64 b, u64 c) {
    u64 d;
    asm("fma.rn.f32x2 %0, %1, %2, %3;" : "=l"(d) : "l"(a), "l"(b), "l"(c));
    return d;
}
__device__ __forceinline__ u64 mul2(u64 a, u64 b) {
    u64 d;
    asm("mul.rn.f32x2 %0, %1, %2;" : "=l"(d) : "l"(a), "l"(b));
    return d;
}

// All 25 taps of input-row (s) into the 5 pending output slots. I = s mod 5.
// kr==0 hits the slot that was just stored: first tap overwrites (mul).
template<int I>
__device__ __forceinline__ void accstep(u64 acc[5][4],
                                        const u64* __restrict__ wp,
                                        const u64* __restrict__ p) {
    #pragma unroll
    for (int kr = 0; kr < 5; kr++) {
        const int slot = ((I - kr) % 5 + 5) % 5;
        #pragma unroll
        for (int t = 0; t < 5; t++) {
            #pragma unroll
            for (int pj = 0; pj < 4; pj++) {
                if (kr == 0 && t == 0)
                    acc[slot][pj] = mul2(wp[0], p[2 * pj]);
                else
                    acc[slot][pj] = fma2(wp[kr * 5 + t], p[2 * pj + t], acc[slot][pj]);
            }
        }
    }
}

__global__ __launch_bounds__(128, 6) void conv5x5_kernel(
    const float* __restrict__ X,
    const float* __restrict__ Kw,
    float* __restrict__ Out)
{
    const int lane  = threadIdx.x;
    const int wrp   = threadIdx.y;                  // 0..3
    const int c     = blockIdx.z;
    const int warpX = blockIdx.x;                   // 0..1
    const int strip = blockIdx.y * 4 + wrp;         // 0..31
    const int Y0    = strip * R;
    const int x0    = warpX * 256 + lane * 8;

    const bool hasL = (x0 >= 2);            // false only for x0 == 0
    const bool hasR = (x0 + 9 < IMG);       // false only for x0 == 504

    const float* __restrict__ Xc = X   + (size_t)c * (IMG * IMG);
    float*       __restrict__ Oc = Out + (size_t)c * (IMG * IMG);

    // packed (w,w) weights (warp-uniform -> UR promotion)
    u64 wp[25];
    #pragma unroll
    for (int i = 0; i < 25; i++) { const float wv = __ldg(&Kw[i]); wp[i] = pk(wv, wv); }

    u64 acc[5][4];
    #pragma unroll
    for (int j = 0; j < 5; j++)
        #pragma unroll
        for (int q = 0; q < 4; q++) acc[j][q] = 0ull;   // one-time; rotation uses mul

    u64 p[11];
    float2 H0b[2], H1b[2];      // halo pairs  v[-2,-1] and v[8,9]
    float4 Ab[2],  Bb[2];       // own 8 floats v[0..7]

// Load input row for step S into buffer PAR (zero outside image / past strip).
#define LOADROW(S, PAR) do {                                                   \
    const int s__ = (S);                                                       \
    const int gy_ = Y0 - 2 + s__;                                              \
    H0b[PAR] = make_float2(0.f, 0.f); H1b[PAR] = make_float2(0.f, 0.f);        \
    Ab[PAR]  = make_float4(0.f,0.f,0.f,0.f);                                   \
    Bb[PAR]  = make_float4(0.f,0.f,0.f,0.f);                                   \
    if (s__ < NSTEP && (unsigned)gy_ < (unsigned)IMG) {                        \
        const float* rp_ = Xc + (size_t)gy_ * IMG + x0;                        \
        Ab[PAR] = *reinterpret_cast<const float4*>(rp_);                       \
        Bb[PAR] = *reinterpret_cast<const float4*>(rp_ + 4);                   \
        if (hasL) H0b[PAR] = *reinterpret_cast<const float2*>(rp_ - 2);        \
        if (hasR) H1b[PAR] = *reinterpret_cast<const float2*>(rp_ + 8);        \
    }                                                                          \
} while (0)

// Pack buffer PAR into p[0..10]; even pairs bit-cast aligned load pairs
// (register-aliased, no MOVs); only the 5 odd pairs materialize.
#define PACKROW(PAR) do {                                                      \
    p[0]  = pk2(H0b[PAR]);                                                     \
    p[1]  = pk(H0b[PAR].y, Ab[PAR].x);                                         \
    p[2]  = pk(Ab[PAR].x,  Ab[PAR].y);                                         \
    p[3]  = pk(Ab[PAR].y,  Ab[PAR].z);                                         \
    p[4]  = pk(Ab[PAR].z,  Ab[PAR].w);                                         \
    p[5]  = pk(Ab[PAR].w,  Bb[PAR].x);                                         \
    p[6]  = pk(Bb[PAR].x,  Bb[PAR].y);                                         \
    p[7]  = pk(Bb[PAR].y,  Bb[PAR].z);                                         \
    p[8]  = pk(Bb[PAR].z,  Bb[PAR].w);                                         \
    p[9]  = pk(Bb[PAR].w,  H1b[PAR].x);                                        \
    p[10] = pk2(H1b[PAR]);                                                     \
} while (0)

// Step s = sb + I: prefetch row s+2 into buf[s&1]; FMA row s (in p);
// store completed row s-4 (slot (I+1)%5) straight from acc; pack row s+1.
#define STEP(I) do {                                                           \
    const int s_ = sb + (I);                                                   \
    LOADROW(s_ + 2, ((I) & 1));                                                \
    accstep<((I) % 5)>(acc, wp, p);                                            \
    if (s_ >= 4) {                                                             \
        float* op_ = Oc + (size_t)(Y0 + s_ - 4) * IMG + x0;                    \
        *reinterpret_cast<ulonglong2*>(op_) =                                  \
            *reinterpret_cast<ulonglong2*>(&acc[((I)+1)%5][0]);                \
        *reinterpret_cast<ulonglong2*>(op_ + 4) =                              \
            *reinterpret_cast<ulonglong2*>(&acc[((I)+1)%5][2]);                \
    }                                                                          \
    PACKROW(((I)+1) & 1);                                                      \
} while (0)

    // prologue: rows 0,1 into buffers; pack row 0
    LOADROW(0, 0);
    LOADROW(1, 1);
    PACKROW(0);

    // 20 steps in unroll-10 blocks (sb = 0, 10)
    #pragma unroll 1
    for (int sb = 0; sb < NSTEP; sb += 10) {
        STEP(0); STEP(1); STEP(2); STEP(3); STEP(4);
        STEP(5); STEP(6); STEP(7); STEP(8); STEP(9);
    }

#undef STEP
#undef PACKROW
#undef LOADROW
}

extern "C" void kernel_launch(void* const* d_in, const int* in_sizes, int n_in,
                              void* d_out, int out_size)
{
    const float* X  = (const float*)d_in[0];
    const float* Kw = (const float*)d_in[1];
    float* Out      = (float*)d_out;

    dim3 grid(2, IMG / R / 4, 128);   // 2 x-halves, 8 strip-groups, 128 planes = 2048 CTAs
    dim3 block(32, 4);                // 4 warps, each owns one 256x16 strip
    conv5x5_kernel<<<grid, block>>>(X, Kw, Out);
}

// round 8
// speedup vs baseline: 1.2025x; 1.2025x over previous
#include <cuda_runtime.h>

// Per-channel 5x5 correlation, stride=1, pad=2; 128 planes of 512x512 f32.
// Register-rolling, 4 warps/CTA, warp owns a 256-wide x 16-row strip.
//   - per input row: 2 aligned LDG.128 + 4 warp shuffles for +-2 x halo
//     (warp-edge lanes do tiny predicated float2 gmem loads).
//   - DEPTH-3 row prefetch (triple-buffered raw regs, index = row % 3,
//     compile-time via full 20-step unroll).
//   - 5 pending output rows in registers, mod-5 rotation; a slot's first tap
//     is mul.f32x2 (no zeroing); completed row stored straight from acc.
//   - packed f32x2 FMA: 100 FMA2/MUL2 per row-step (8 outputs wide).

#define IMG  512
#define R    16
#define NSTEP (R + 4)      // 20 input rows per strip
#define FULLMASK 0xffffffffu

typedef unsigned long long u64;

__device__ __forceinline__ u64 pk(float lo, float hi) {
    u64 r;
    asm("mov.b64 %0, {%1, %2};" : "=l"(r) : "f"(lo), "f"(hi));
    return r;
}
__device__ __forceinline__ u64 fma2(u64 a, u64 b, u64 c) {
    u64 d;
    asm("fma.rn.f32x2 %0, %1, %2, %3;" : "=l"(d) : "l"(a), "l"(b), "l"(c));
    return d;
}
__device__ __forceinline__ u64 mul2(u64 a, u64 b) {
    u64 d;
    asm("mul.rn.f32x2 %0, %1, %2;" : "=l"(d) : "l"(a), "l"(b));
    return d;
}

// All 25 taps of input-row (s) into the 5 pending output slots. I = s mod 5.
// kr==0 hits the slot whose previous output was just stored: first tap
// overwrites via mul (no explicit zeroing needed).
template<int I>
__device__ __forceinline__ void accstep(u64 acc[5][4],
                                        const u64* __restrict__ wp,
                                        const u64* __restrict__ p) {
    #pragma unroll
    for (int kr = 0; kr < 5; kr++) {
        const int slot = ((I - kr) % 5 + 5) % 5;
        #pragma unroll
        for (int t = 0; t < 5; t++) {
            #pragma unroll
            for (int pj = 0; pj < 4; pj++) {
                if (kr == 0 && t == 0)
                    acc[slot][pj] = mul2(wp[0], p[2 * pj]);
                else
                    acc[slot][pj] = fma2(wp[kr * 5 + t], p[2 * pj + t], acc[slot][pj]);
            }
        }
    }
}

__global__ __launch_bounds__(128, 5) void conv5x5_kernel(
    const float* __restrict__ X,
    const float* __restrict__ Kw,
    float* __restrict__ Out)
{
    const int lane  = threadIdx.x;
    const int wrp   = threadIdx.y;                  // 0..3
    const int c     = blockIdx.z;
    const int warpX = blockIdx.x;                   // 0..1
    const int strip = blockIdx.y * 4 + wrp;         // 0..31
    const int Y0    = strip * R;
    const int x0    = warpX * 256 + lane * 8;

    const float* __restrict__ Xc = X   + (size_t)c * (IMG * IMG);
    float*       __restrict__ Oc = Out + (size_t)c * (IMG * IMG);

    // packed (w,w) weights (warp-uniform -> UR promotion)
    u64 wp[25];
    #pragma unroll
    for (int i = 0; i < 25; i++) { const float wv = __ldg(&Kw[i]); wp[i] = pk(wv, wv); }

    u64 acc[5][4];
    #pragma unroll
    for (int j = 0; j < 5; j++)
        #pragma unroll
        for (int q = 0; q < 4; q++) acc[j][q] = 0ull;   // one-time; rotation uses mul

    u64 p[11];
    float4 Ab[3], Bb[3];        // triple-buffered raw rows (index = row % 3)
    float2 LFb[3], RFb[3];

// Load input row ROWS into buffer PAR (zero outside image).
#define LOADROW(ROWS, PAR) do {                                                \
    const int gy_ = Y0 - 2 + (ROWS);                                           \
    Ab[PAR] = make_float4(0.f,0.f,0.f,0.f); Bb[PAR] = make_float4(0.f,0.f,0.f,0.f); \
    LFb[PAR] = make_float2(0.f,0.f); RFb[PAR] = make_float2(0.f,0.f);          \
    if ((unsigned)gy_ < (unsigned)IMG) {                                       \
        const float* rp_ = Xc + (size_t)gy_ * IMG + x0;                        \
        Ab[PAR] = *reinterpret_cast<const float4*>(rp_);                       \
        Bb[PAR] = *reinterpret_cast<const float4*>(rp_ + 4);                   \
        if (lane == 0  && x0 >= 2)      LFb[PAR] = *reinterpret_cast<const float2*>(rp_ - 2); \
        if (lane == 31 && x0 + 9 < IMG) RFb[PAR] = *reinterpret_cast<const float2*>(rp_ + 8); \
    }                                                                          \
} while (0)

// Shuffle halo + pack buffer PAR into p[0..10].
#define PACKROW(PAR) do {                                                      \
    float l0_ = __shfl_up_sync(FULLMASK,  Bb[PAR].z, 1);                       \
    float l1_ = __shfl_up_sync(FULLMASK,  Bb[PAR].w, 1);                       \
    float r0_ = __shfl_down_sync(FULLMASK, Ab[PAR].x, 1);                      \
    float r1_ = __shfl_down_sync(FULLMASK, Ab[PAR].y, 1);                      \
    if (lane == 0)  { l0_ = LFb[PAR].x; l1_ = LFb[PAR].y; }                    \
    if (lane == 31) { r0_ = RFb[PAR].x; r1_ = RFb[PAR].y; }                    \
    p[0]  = pk(l0_, l1_);             p[1]  = pk(l1_, Ab[PAR].x);              \
    p[2]  = pk(Ab[PAR].x, Ab[PAR].y); p[3]  = pk(Ab[PAR].y, Ab[PAR].z);        \
    p[4]  = pk(Ab[PAR].z, Ab[PAR].w); p[5]  = pk(Ab[PAR].w, Bb[PAR].x);        \
    p[6]  = pk(Bb[PAR].x, Bb[PAR].y); p[7]  = pk(Bb[PAR].y, Bb[PAR].z);        \
    p[8]  = pk(Bb[PAR].z, Bb[PAR].w); p[9]  = pk(Bb[PAR].w, r0_);              \
    p[10] = pk(r0_, r1_);                                                      \
} while (0)

// Step S (literal 0..19): prefetch row S+3; FMA row S (in p); store completed
// output row S-4 straight from acc slot (S+1)%5; pack row S+1 into p.
#define STEPX(S) do {                                                          \
    if ((S) + 3 < NSTEP) LOADROW((S) + 3, ((S) + 3) % 3);                      \
    accstep<(S) % 5>(acc, wp, p);                                              \
    if ((S) >= 4) {                                                            \
        float* op_ = Oc + (size_t)(Y0 + (S) - 4) * IMG + x0;                   \
        *reinterpret_cast<ulonglong2*>(op_) =                                  \
            *reinterpret_cast<ulonglong2*>(&acc[((S)+1)%5][0]);                \
        *reinterpret_cast<ulonglong2*>(op_ + 4) =                              \
            *reinterpret_cast<ulonglong2*>(&acc[((S)+1)%5][2]);                \
    }                                                                          \
    if ((S) + 1 < NSTEP) PACKROW(((S) + 1) % 3);                               \
} while (0)

    // prologue: rows 0,1,2 into buffers; pack row 0
    LOADROW(0, 0);
    LOADROW(1, 1);
    LOADROW(2, 2);
    PACKROW(0);

    // 20 fully-unrolled steps (all %3 / %5 indices compile-time)
    STEPX(0);  STEPX(1);  STEPX(2);  STEPX(3);  STEPX(4);
    STEPX(5);  STEPX(6);  STEPX(7);  STEPX(8);  STEPX(9);
    STEPX(10); STEPX(11); STEPX(12); STEPX(13); STEPX(14);
    STEPX(15); STEPX(16); STEPX(17); STEPX(18); STEPX(19);

#undef STEPX
#undef PACKROW
#undef LOADROW
}

extern "C" void kernel_launch(void* const* d_in, const int* in_sizes, int n_in,
                              void* d_out, int out_size)
{
    const float* X  = (const float*)d_in[0];
    const float* Kw = (const float*)d_in[1];
    float* Out      = (float*)d_out;

    dim3 grid(2, IMG / R / 4, 128);   // 2 x-halves, 8 strip-groups, 128 planes = 2048 CTAs
    dim3 block(32, 4);                // 4 warps, each owns one 256x16 strip
    conv5x5_kernel<<<grid, block>>>(X, Kw, Out);
}

// round 9
// speedup vs baseline: 1.2880x; 1.0711x over previous
#include <cuda_runtime.h>
#include <string.h>

// Per-channel 5x5 correlation, stride=1, pad=2; 128 planes of 512x512 f32.
// Register-rolling, 4 warps/CTA, warp owns a 256-wide x 16-row strip.
//   - per input row: 2 aligned LDG.128 + 4 warp shuffles for +-2 x halo
//     (warp-edge lanes do tiny predicated float2 gmem loads).
//   - depth-2 row prefetch (double-buffered raw regs, parity compile-time).
//   - 5 pending output rows in registers, mod-5 rotation; slot's FIRST tap is
//     mul.f32x2 (no zeroing); completed row stored straight from acc.
//   - f32x2 packing via memcpy bit-cast: the 6 even-aligned pairs alias the
//     vector-load registers (no MOVs); only 5 odd pairs materialize.
//   - hot loop = two 10-step blocks (I$-safe; full unroll regressed in R8).

#define IMG  512
#define R    16
#define NSTEP (R + 4)      // 20 input rows per strip
#define FULLMASK 0xffffffffu

typedef unsigned long long u64;

__device__ __forceinline__ u64 pk(float lo, float hi) {
    float2 t; t.x = lo; t.y = hi;
    u64 r; memcpy(&r, &t, 8);
    return r;
}
__device__ __forceinline__ u64 pk2(float2 t) {
    u64 r; memcpy(&r, &t, 8);
    return r;
}
__device__ __forceinline__ u64 fma2(u64 a, u64 b, u64 c) {
    u64 d;
    asm("fma.rn.f32x2 %0, %1, %2, %3;" : "=l"(d) : "l"(a), "l"(b), "l"(c));
    return d;
}
__device__ __forceinline__ u64 mul2(u64 a, u64 b) {
    u64 d;
    asm("mul.rn.f32x2 %0, %1, %2;" : "=l"(d) : "l"(a), "l"(b));
    return d;
}

// All 25 taps of input-row (s) into the 5 pending output slots. I = s mod 5.
// kr==0 hits the slot whose previous output was just stored: first tap
// overwrites via mul (no explicit zeroing needed).
template<int I>
__device__ __forceinline__ void accstep(u64 acc[5][4],
                                        const u64* __restrict__ wp,
                                        const u64* __restrict__ p) {
    #pragma unroll
    for (int kr = 0; kr < 5; kr++) {
        const int slot = ((I - kr) % 5 + 5) % 5;
        #pragma unroll
        for (int t = 0; t < 5; t++) {
            #pragma unroll
            for (int pj = 0; pj < 4; pj++) {
                if (kr == 0 && t == 0)
                    acc[slot][pj] = mul2(wp[0], p[2 * pj]);
                else
                    acc[slot][pj] = fma2(wp[kr * 5 + t], p[2 * pj + t], acc[slot][pj]);
            }
        }
    }
}

__global__ __launch_bounds__(128, 5) void conv5x5_kernel(
    const float* __restrict__ X,
    const float* __restrict__ Kw,
    float* __restrict__ Out)
{
    const int lane  = threadIdx.x;
    const int wrp   = threadIdx.y;                  // 0..3
    const int c     = blockIdx.z;
    const int warpX = blockIdx.x;                   // 0..1
    const int strip = blockIdx.y * 4 + wrp;         // 0..31
    const int Y0    = strip * R;
    const int x0    = warpX * 256 + lane * 8;

    const float* __restrict__ Xc = X   + (size_t)c * (IMG * IMG);
    float*       __restrict__ Oc = Out + (size_t)c * (IMG * IMG);

    // packed (w,w) weights (warp-uniform -> UR promotion)
    u64 wp[25];
    #pragma unroll
    for (int i = 0; i < 25; i++) { const float wv = __ldg(&Kw[i]); wp[i] = pk(wv, wv); }

    u64 acc[5][4];
    #pragma unroll
    for (int j = 0; j < 5; j++)
        #pragma unroll
        for (int q = 0; q < 4; q++) acc[j][q] = 0ull;   // one-time; rotation uses mul

    u64 p[11];
    float4 Ab[2], Bb[2];      // double-buffered raw rows
    float2 LFb[2], RFb[2];

// Load input row for step S into buffer PAR (zero outside image / past strip).
#define LOADROW(S, PAR) do {                                                   \
    const int s__ = (S);                                                       \
    const int gy_ = Y0 - 2 + s__;                                              \
    Ab[PAR] = make_float4(0.f,0.f,0.f,0.f); Bb[PAR] = make_float4(0.f,0.f,0.f,0.f); \
    LFb[PAR] = make_float2(0.f,0.f); RFb[PAR] = make_float2(0.f,0.f);          \
    if (s__ < NSTEP && (unsigned)gy_ < (unsigned)IMG) {                        \
        const float* rp_ = Xc + (size_t)gy_ * IMG + x0;                        \
        Ab[PAR] = *reinterpret_cast<const float4*>(rp_);                       \
        Bb[PAR] = *reinterpret_cast<const float4*>(rp_ + 4);                   \
        if (lane == 0  && x0 >= 2)      LFb[PAR] = *reinterpret_cast<const float2*>(rp_ - 2); \
        if (lane == 31 && x0 + 9 < IMG) RFb[PAR] = *reinterpret_cast<const float2*>(rp_ + 8); \
    }                                                                          \
} while (0)

// Shuffle halo + pack buffer PAR into p[0..10].
// Even pairs bit-cast aligned vector-load pairs (register-aliased, no MOVs).
#define PACKROW(PAR) do {                                                      \
    float l0_ = __shfl_up_sync(FULLMASK,  Bb[PAR].z, 1);                       \
    float l1_ = __shfl_up_sync(FULLMASK,  Bb[PAR].w, 1);                       \
    float r0_ = __shfl_down_sync(FULLMASK, Ab[PAR].x, 1);                      \
    float r1_ = __shfl_down_sync(FULLMASK, Ab[PAR].y, 1);                      \
    if (lane == 0)  { l0_ = LFb[PAR].x; l1_ = LFb[PAR].y; }                    \
    if (lane == 31) { r0_ = RFb[PAR].x; r1_ = RFb[PAR].y; }                    \
    p[0]  = pk(l0_, l1_);                                                      \
    p[1]  = pk(l1_, Ab[PAR].x);                                                \
    p[2]  = pk(Ab[PAR].x, Ab[PAR].y);                                          \
    p[3]  = pk(Ab[PAR].y, Ab[PAR].z);                                          \
    p[4]  = pk(Ab[PAR].z, Ab[PAR].w);                                          \
    p[5]  = pk(Ab[PAR].w, Bb[PAR].x);                                          \
    p[6]  = pk(Bb[PAR].x, Bb[PAR].y);                                          \
    p[7]  = pk(Bb[PAR].y, Bb[PAR].z);                                          \
    p[8]  = pk(Bb[PAR].z, Bb[PAR].w);                                          \
    p[9]  = pk(Bb[PAR].w, r0_);                                                \
    p[10] = pk(r0_, r1_);                                                      \
} while (0)

// Step s = sb + I: prefetch row s+2 into buf[s&1]; FMA row s (in p);
// store completed row s-4 (slot (I+1)%5) straight from acc; pack row s+1.
#define STEP(I) do {                                                           \
    const int s_ = sb + (I);                                                   \
    LOADROW(s_ + 2, ((I) & 1));                                                \
    accstep<((I) % 5)>(acc, wp, p);                                            \
    if (s_ >= 4) {                                                             \
        float* op_ = Oc + (size_t)(Y0 + s_ - 4) * IMG + x0;                    \
        *reinterpret_cast<ulonglong2*>(op_) =                                  \
            *reinterpret_cast<ulonglong2*>(&acc[((I)+1)%5][0]);                \
        *reinterpret_cast<ulonglong2*>(op_ + 4) =                              \
            *reinterpret_cast<ulonglong2*>(&acc[((I)+1)%5][2]);                \
    }                                                                          \
    PACKROW(((I)+1) & 1);                                                      \
} while (0)

    // prologue: rows 0,1 into buffers; pack row 0
    LOADROW(0, 0);
    LOADROW(1, 1);
    PACKROW(0);

    // 20 steps in unroll-10 blocks (sb = 0, 10) — keeps SASS inside I$
    #pragma unroll 1
    for (int sb = 0; sb < NSTEP; sb += 10) {
        STEP(0); STEP(1); STEP(2); STEP(3); STEP(4);
        STEP(5); STEP(6); STEP(7); STEP(8); STEP(9);
    }

#undef STEP
#undef PACKROW
#undef LOADROW
}

extern "C" void kernel_launch(void* const* d_in, const int* in_sizes, int n_in,
                              void* d_out, int out_size)
{
    const float* X  = (const float*)d_in[0];
    const float* Kw = (const float*)d_in[1];
    float* Out      = (float*)d_out;

    dim3 grid(2, IMG / R / 4, 128);   // 2 x-halves, 8 strip-groups, 128 planes = 2048 CTAs
    dim3 block(32, 4);                // 4 warps, each owns one 256x16 strip
    conv5x5_kernel<<<grid, block>>>(X, Kw, Out);
}

// round 10
// speedup vs baseline: 1.3090x; 1.0163x over previous
#include <cuda_runtime.h>
#include <string.h>

// Per-channel 5x5 correlation, stride=1, pad=2; 128 planes of 512x512 f32.
// Register-rolling accumulation + cp.async smem row ring:
//   - 4 warps/CTA; warp owns a 256-wide x 16-row strip; lane owns 8 x.
//   - per-warp 5-slot smem ring of input rows (264 floats = 1056 B each),
//     filled by cp.async.ca 16B chunks, depth-3 prefetch, commit/wait_group 3
//     (empty commit_groups keep the group count uniform at the tail).
//   - out-of-image rows / edge chunks zero-filled via predicated STS.
//   - per step: LDS.64 + 2x LDS.128 + LDS.64 give v[-2..9]; 6 even f32x2
//     pairs are the aligned load results (no MOVs), 5 odd pairs materialize.
//   - 5 pending output rows in registers, mod-5 rotation; slot's first tap is
//     mul.f32x2; completed row stored straight from acc.
//   - hot loop = two 10-step blocks (ring=5 keeps slots compile-time).

#define IMG   512
#define R     16
#define NSTEP (R + 4)          // 20 input rows per strip
#define ROWB  1056             // 264 floats per staged row
#define RING  5
#define WSM   (RING * ROWB)    // 5280 B per warp

typedef unsigned long long u64;

__device__ __forceinline__ u64 pk(float lo, float hi) {
    float2 t; t.x = lo; t.y = hi;
    u64 r; memcpy(&r, &t, 8);
    return r;
}
__device__ __forceinline__ u64 pk2(float2 t) {
    u64 r; memcpy(&r, &t, 8);
    return r;
}
__device__ __forceinline__ u64 fma2(u64 a, u64 b, u64 c) {
    u64 d;
    asm("fma.rn.f32x2 %0, %1, %2, %3;" : "=l"(d) : "l"(a), "l"(b), "l"(c));
    return d;
}
__device__ __forceinline__ u64 mul2(u64 a, u64 b) {
    u64 d;
    asm("mul.rn.f32x2 %0, %1, %2;" : "=l"(d) : "l"(a), "l"(b));
    return d;
}
__device__ __forceinline__ void cpa16(unsigned d, const void* g) {
    asm volatile("cp.async.ca.shared.global [%0], [%1], 16;" :: "r"(d), "l"(g));
}
__device__ __forceinline__ void stsz(unsigned a) {
    asm volatile("st.shared.v4.u32 [%0], {%1,%1,%1,%1};" :: "r"(a), "r"(0u));
}

// All 25 taps of input-row (s) into the 5 pending output slots. I = s mod 5.
// kr==0 hits the just-stored slot: first tap overwrites via mul (no zeroing).
template<int I>
__device__ __forceinline__ void accstep(u64 acc[5][4],
                                        const u64* __restrict__ wp,
                                        const u64* __restrict__ p) {
    #pragma unroll
    for (int kr = 0; kr < 5; kr++) {
        const int slot = ((I - kr) % 5 + 5) % 5;
        #pragma unroll
        for (int t = 0; t < 5; t++) {
            #pragma unroll
            for (int pj = 0; pj < 4; pj++) {
                if (kr == 0 && t == 0)
                    acc[slot][pj] = mul2(wp[0], p[2 * pj]);
                else
                    acc[slot][pj] = fma2(wp[kr * 5 + t], p[2 * pj + t], acc[slot][pj]);
            }
        }
    }
}

__global__ __launch_bounds__(128, 6) void conv5x5_kernel(
    const float* __restrict__ X,
    const float* __restrict__ Kw,
    float* __restrict__ Out)
{
    __shared__ __align__(16) char ring[4 * WSM];

    const int lane  = threadIdx.x;
    const int wrp   = threadIdx.y;                  // 0..3
    const int c     = blockIdx.z;
    const int warpX = blockIdx.x;                   // 0..1
    const int strip = blockIdx.y * 4 + wrp;         // 0..31
    const int Y0    = strip * R;
    const int x0w   = warpX * 256;                  // warp x base
    const int x0    = x0w + lane * 8;               // lane x base

    const float* __restrict__ Xc = X   + (size_t)c * (IMG * IMG);
    float*       __restrict__ Oc = Out + (size_t)c * (IMG * IMG);

    const char* wring = ring + wrp * WSM;                       // generic, for LDS
    const unsigned sbase =
        (unsigned)__cvta_generic_to_shared(ring) + wrp * WSM;   // for cp.async/STS

    // packed (w,w) weights (warp-uniform -> UR promotion)
    u64 wp[25];
    #pragma unroll
    for (int i = 0; i < 25; i++) { const float wv = __ldg(&Kw[i]); wp[i] = pk(wv, wv); }

    u64 acc[5][4];
    #pragma unroll
    for (int j = 0; j < 5; j++)
        #pragma unroll
        for (int q = 0; q < 4; q++) acc[j][q] = 0ull;   // one-time; rotation uses mul

    u64 p[11];

// Issue the async fill of input row ROWI into ring slot SLOT, always ending
// with a commit_group (possibly empty) so group counting stays uniform.
// Staged row covers global x = x0w-4 .. x0w+259 (66 x 16B chunks).
// chunk 0 is out-of-image for warpX==0; chunk 65 for warpX==1.
#define ISSUE_ROW(ROWI, SLOT) do {                                             \
    const int row_ = (ROWI);                                                   \
    if (row_ < NSTEP) {                                                        \
        const int gy_ = Y0 - 2 + row_;                                         \
        const unsigned sb_ = sbase + (SLOT) * ROWB;                            \
        if ((unsigned)gy_ < (unsigned)IMG) {                                   \
            const char* gs_ = (const char*)(Xc + (size_t)gy_ * IMG + x0w - 4); \
            { const int c0_ = lane;                                            \
              if (c0_ != 0 || warpX != 0) cpa16(sb_ + c0_ * 16, gs_ + c0_ * 16); \
              else                        stsz(sb_ + c0_ * 16); }              \
            { const int c1_ = 32 + lane;                                       \
              cpa16(sb_ + c1_ * 16, gs_ + c1_ * 16); }                         \
            if (lane < 2) {                                                    \
                const int c2_ = 64 + lane;                                     \
                if (c2_ != 65 || warpX != 1) cpa16(sb_ + c2_ * 16, gs_ + c2_ * 16); \
                else                         stsz(sb_ + c2_ * 16);             \
            }                                                                  \
        } else {                                                               \
            stsz(sb_ + lane * 16);                                             \
            stsz(sb_ + 512 + lane * 16);                                       \
            if (lane < 2) stsz(sb_ + 1024 + lane * 16);                        \
        }                                                                      \
    }                                                                          \
    asm volatile("cp.async.commit_group;");                                    \
} while (0)

// Read ring slot SLOT and pack p[0..10]. Lane's window v[-2..9] sits at byte
// offsets lane*32+8 .. +55 within the row. Even pairs = aligned load results.
#define READPACK(SLOT) do {                                                    \
    const char* b_ = wring + (SLOT) * ROWB + lane * 32;                        \
    const float2 h0 = *reinterpret_cast<const float2*>(b_ + 8);                \
    const float4 A  = *reinterpret_cast<const float4*>(b_ + 16);               \
    const float4 B  = *reinterpret_cast<const float4*>(b_ + 32);               \
    const float2 h1 = *reinterpret_cast<const float2*>(b_ + 48);               \
    p[0]  = pk2(h0);                                                           \
    p[1]  = pk(h0.y, A.x);                                                     \
    p[2]  = pk(A.x,  A.y);                                                     \
    p[3]  = pk(A.y,  A.z);                                                     \
    p[4]  = pk(A.z,  A.w);                                                     \
    p[5]  = pk(A.w,  B.x);                                                     \
    p[6]  = pk(B.x,  B.y);                                                     \
    p[7]  = pk(B.y,  B.z);                                                     \
    p[8]  = pk(B.z,  B.w);                                                     \
    p[9]  = pk(B.w,  h1.x);                                                    \
    p[10] = pk2(h1);                                                           \
} while (0)

// Step s = sb + I (sb % 10 == 0 -> all %5 slots compile-time):
//   issue fill of row s+3; wait until row s complete; read+pack row s;
//   accumulate; store completed output row s-4 straight from acc.
#define STEP(I) do {                                                           \
    const int s_ = sb + (I);                                                   \
    ISSUE_ROW(s_ + 3, ((I) + 3) % 5);                                          \
    asm volatile("cp.async.wait_group 3;");                                    \
    __syncwarp();                                                              \
    READPACK((I) % 5);                                                         \
    accstep<((I) % 5)>(acc, wp, p);                                            \
    if (s_ >= 4) {                                                             \
        float* op_ = Oc + (size_t)(Y0 + s_ - 4) * IMG + x0;                    \
        *reinterpret_cast<ulonglong2*>(op_) =                                  \
            *reinterpret_cast<ulonglong2*>(&acc[((I)+1)%5][0]);                \
        *reinterpret_cast<ulonglong2*>(op_ + 4) =                              \
            *reinterpret_cast<ulonglong2*>(&acc[((I)+1)%5][2]);                \
    }                                                                          \
} while (0)

    // prologue: issue rows 0,1,2 (three groups)
    ISSUE_ROW(0, 0);
    ISSUE_ROW(1, 1);
    ISSUE_ROW(2, 2);

    // 20 steps in unroll-10 blocks (sb = 0, 10) — keeps SASS inside I$
    #pragma unroll 1
    for (int sb = 0; sb < NSTEP; sb += 10) {
        STEP(0); STEP(1); STEP(2); STEP(3); STEP(4);
        STEP(5); STEP(6); STEP(7); STEP(8); STEP(9);
    }

#undef STEP
#undef READPACK
#undef ISSUE_ROW
}

extern "C" void kernel_launch(void* const* d_in, const int* in_sizes, int n_in,
                              void* d_out, int out_size)
{
    const float* X  = (const float*)d_in[0];
    const float* Kw = (const float*)d_in[1];
    float* Out      = (float*)d_out;

    dim3 grid(2, IMG / R / 4, 128);   // 2 x-halves, 8 strip-groups, 128 planes = 2048 CTAs
    dim3 block(32, 4);                // 4 warps, each owns one 256x16 strip
    conv5x5_kernel<<<grid, block>>>(X, Kw, Out);
}

// round 11
// speedup vs baseline: 1.3901x; 1.0619x over previous
#include <cuda_runtime.h>
#include <string.h>

// Per-channel 5x5 correlation, stride=1, pad=2; 128 planes of 512x512 f32.
// Register-rolling accumulation + cp.async smem row ring (R10 base), plus:
//   - PARTIAL prologue/epilogue accsteps: step s only runs kernel rows
//     kr in [max(0,s-15), min(4,s)] -> 1600 instead of 2000 FMA2 per strip
//     (bit-identical results; garbage-slot work eliminated).
//   - depth-4 cp.async prefetch (ring 5 slots, wait_group 4).
//   - edge x-chunks (chunk 0 for warpX==0, chunk 65 for warpX==1) zeroed
//     ONCE before the loop; per-step fills skip them.

#define IMG   512
#define R     16
#define NSTEP (R + 4)          // 20 input rows per strip
#define ROWB  1056             // 264 floats per staged row
#define RING  5
#define WSM   (RING * ROWB)    // 5280 B per warp

typedef unsigned long long u64;

__device__ __forceinline__ u64 pk(float lo, float hi) {
    float2 t; t.x = lo; t.y = hi;
    u64 r; memcpy(&r, &t, 8);
    return r;
}
__device__ __forceinline__ u64 pk2(float2 t) {
    u64 r; memcpy(&r, &t, 8);
    return r;
}
__device__ __forceinline__ u64 fma2(u64 a, u64 b, u64 c) {
    u64 d;
    asm("fma.rn.f32x2 %0, %1, %2, %3;" : "=l"(d) : "l"(a), "l"(b), "l"(c));
    return d;
}
__device__ __forceinline__ u64 mul2(u64 a, u64 b) {
    u64 d;
    asm("mul.rn.f32x2 %0, %1, %2;" : "=l"(d) : "l"(a), "l"(b));
    return d;
}
__device__ __forceinline__ void cpa16(unsigned d, const void* g) {
    asm volatile("cp.async.ca.shared.global [%0], [%1], 16;" :: "r"(d), "l"(g));
}
__device__ __forceinline__ void stsz(unsigned a) {
    asm volatile("st.shared.v4.u32 [%0], {%1,%1,%1,%1};" :: "r"(a), "r"(0u));
}

// Taps of input-row s (I = s mod 5) into pending output slots, restricted to
// kernel rows kr in [KRLO, KRHI]. Output o = s - kr lives in slot o % 5.
// kr==0 is an output's chronologically FIRST contribution: overwrite via mul.
template<int I, int KRLO, int KRHI>
__device__ __forceinline__ void accstep(u64 acc[5][4],
                                        const u64* __restrict__ wp,
                                        const u64* __restrict__ p) {
    #pragma unroll
    for (int kr = KRLO; kr <= KRHI; kr++) {
        const int slot = ((I - kr) % 5 + 5) % 5;
        #pragma unroll
        for (int t = 0; t < 5; t++) {
            #pragma unroll
            for (int pj = 0; pj < 4; pj++) {
                if (kr == 0 && t == 0)
                    acc[slot][pj] = mul2(wp[0], p[2 * pj]);
                else
                    acc[slot][pj] = fma2(wp[kr * 5 + t], p[2 * pj + t], acc[slot][pj]);
            }
        }
    }
}

__global__ __launch_bounds__(128, 6) void conv5x5_kernel(
    const float* __restrict__ X,
    const float* __restrict__ Kw,
    float* __restrict__ Out)
{
    __shared__ __align__(16) char ring[4 * WSM];

    const int lane  = threadIdx.x;
    const int wrp   = threadIdx.y;                  // 0..3
    const int c     = blockIdx.z;
    const int warpX = blockIdx.x;                   // 0..1
    const int strip = blockIdx.y * 4 + wrp;         // 0..31
    const int Y0    = strip * R;
    const int x0w   = warpX * 256;                  // warp x base
    const int x0    = x0w + lane * 8;               // lane x base

    const float* __restrict__ Xc = X   + (size_t)c * (IMG * IMG);
    float*       __restrict__ Oc = Out + (size_t)c * (IMG * IMG);

    const char* wring = ring + wrp * WSM;                       // generic, for LDS
    const unsigned sbase =
        (unsigned)__cvta_generic_to_shared(ring) + wrp * WSM;   // for cp.async/STS

    // zero the permanently-out-of-image x-edge chunk of every ring slot ONCE:
    // chunk 0 (x0w-4..-1) for warpX==0, chunk 65 (x 512..515) for warpX==1.
    if (lane < RING)
        stsz(sbase + lane * ROWB + (warpX ? 65 * 16 : 0));
    __syncwarp();

    // packed (w,w) weights (warp-uniform -> UR promotion)
    u64 wp[25];
    #pragma unroll
    for (int i = 0; i < 25; i++) { const float wv = __ldg(&Kw[i]); wp[i] = pk(wv, wv); }

    u64 acc[5][4];
    #pragma unroll
    for (int j = 0; j < 5; j++)
        #pragma unroll
        for (int q = 0; q < 4; q++) acc[j][q] = 0ull;   // slots start via mul anyway

    u64 p[11];

// Issue async fill of row ROWI into ring slot SLOT; always ends with a
// commit_group (possibly empty) so group counting stays uniform.
// Row covers global x = x0w-4 .. x0w+259 (66 x 16B chunks); the one
// permanently-OOB edge chunk is skipped (pre-zeroed above).
#define ISSUE_ROW(ROWI, SLOT) do {                                             \
    const int row_ = (ROWI);                                                   \
    if (row_ < NSTEP) {                                                        \
        const int gy_ = Y0 - 2 + row_;                                         \
        const unsigned sb_ = sbase + (SLOT) * ROWB;                            \
        if ((unsigned)gy_ < (unsigned)IMG) {                                   \
            const char* gs_ = (const char*)(Xc + (size_t)gy_ * IMG + x0w - 4); \
            if ((lane | warpX) != 0)                                           \
                cpa16(sb_ + lane * 16, gs_ + lane * 16);                       \
            cpa16(sb_ + (32 + lane) * 16, gs_ + (32 + lane) * 16);             \
            if (lane + warpX < 2)                                              \
                cpa16(sb_ + (64 + lane) * 16, gs_ + (64 + lane) * 16);         \
        } else {                                                               \
            stsz(sb_ + lane * 16);                                             \
            stsz(sb_ + (32 + lane) * 16);                                      \
            if (lane < 2) stsz(sb_ + (64 + lane) * 16);                        \
        }                                                                      \
    }                                                                          \
    asm volatile("cp.async.commit_group;");                                    \
} while (0)

// Read ring slot SLOT and pack p[0..10]. Lane window v[-2..9] = bytes
// lane*32+8 .. +55. Even pairs = aligned load results (no MOVs).
#define READPACK(SLOT) do {                                                    \
    const char* b_ = wring + (SLOT) * ROWB + lane * 32;                        \
    const float2 h0 = *reinterpret_cast<const float2*>(b_ + 8);                \
    const float4 A  = *reinterpret_cast<const float4*>(b_ + 16);               \
    const float4 B  = *reinterpret_cast<const float4*>(b_ + 32);               \
    const float2 h1 = *reinterpret_cast<const float2*>(b_ + 48);               \
    p[0]  = pk2(h0);                                                           \
    p[1]  = pk(h0.y, A.x);                                                     \
    p[2]  = pk(A.x,  A.y);                                                     \
    p[3]  = pk(A.y,  A.z);                                                     \
    p[4]  = pk(A.z,  A.w);                                                     \
    p[5]  = pk(A.w,  B.x);                                                     \
    p[6]  = pk(B.x,  B.y);                                                     \
    p[7]  = pk(B.y,  B.z);                                                     \
    p[8]  = pk(B.z,  B.w);                                                     \
    p[9]  = pk(B.w,  h1.x);                                                    \
    p[10] = pk2(h1);                                                           \
} while (0)

#define STORE_ROW(S) do {                                                      \
    float* op_ = Oc + (size_t)(Y0 + (S) - 4) * IMG + x0;                       \
    *reinterpret_cast<ulonglong2*>(op_) =                                      \
        *reinterpret_cast<ulonglong2*>(&acc[((S)+1)%5][0]);                    \
    *reinterpret_cast<ulonglong2*>(op_ + 4) =                                  \
        *reinterpret_cast<ulonglong2*>(&acc[((S)+1)%5][2]);                    \
} while (0)

// Generic step with literal S and kr-range: issue row S+4 (depth-4), wait,
// read+pack row S, accumulate only useful kernel rows, store output S-4.
#define PSTEP(S, KRLO, KRHI) do {                                              \
    ISSUE_ROW((S) + 4, ((S) + 4) % 5);                                         \
    asm volatile("cp.async.wait_group 4;");                                    \
    __syncwarp();                                                              \
    READPACK((S) % 5);                                                         \
    accstep<(S) % 5, KRLO, KRHI>(acc, wp, p);                                  \
    if ((S) >= 4) STORE_ROW(S);                                                \
} while (0)

// Loop step: s = sb + J, sb % 5 == 4 -> all mod-5 indices are literals of J.
#define LSTEP(J) do {                                                          \
    const int s_ = sb + (J);                                                   \
    ISSUE_ROW(s_ + 4, ((J) + 3) % 5);                                          \
    asm volatile("cp.async.wait_group 4;");                                    \
    __syncwarp();                                                              \
    READPACK(((J) + 4) % 5);                                                   \
    accstep<((J) + 4) % 5, 0, 4>(acc, wp, p);                                  \
    {                                                                          \
        float* op_ = Oc + (size_t)(Y0 + s_ - 4) * IMG + x0;                    \
        *reinterpret_cast<ulonglong2*>(op_) =                                  \
            *reinterpret_cast<ulonglong2*>(&acc[(J) % 5][0]);                  \
        *reinterpret_cast<ulonglong2*>(op_ + 4) =                              \
            *reinterpret_cast<ulonglong2*>(&acc[(J) % 5][2]);                  \
    }                                                                          \
} while (0)

    // prologue: issue rows 0..3 (4 groups in flight)
    ISSUE_ROW(0, 0);
    ISSUE_ROW(1, 1);
    ISSUE_ROW(2, 2);
    ISSUE_ROW(3, 3);

    // warm-up steps 0..3: only kr <= s feeds real outputs
    PSTEP(0, 0, 0);
    PSTEP(1, 0, 1);
    PSTEP(2, 0, 2);
    PSTEP(3, 0, 3);

    // full steps 4..13 (two 5-blocks; sb = 4, 9)
    #pragma unroll 1
    for (int sb = 4; sb < 14; sb += 5) {
        LSTEP(0); LSTEP(1); LSTEP(2); LSTEP(3); LSTEP(4);
    }

    // full steps 14, 15
    PSTEP(14, 0, 4);
    PSTEP(15, 0, 4);

    // drain steps 16..19: only kr >= s-15 feeds real outputs
    PSTEP(16, 1, 4);
    PSTEP(17, 2, 4);
    PSTEP(18, 3, 4);
    PSTEP(19, 4, 4);

#undef LSTEP
#undef PSTEP
#undef STORE_ROW
#undef READPACK
#undef ISSUE_ROW
}

extern "C" void kernel_launch(void* const* d_in, const int* in_sizes, int n_in,
                              void* d_out, int out_size)
{
    const float* X  = (const float*)d_in[0];
    const float* Kw = (const float*)d_in[1];
    float* Out      = (float*)d_out;

    dim3 grid(2, IMG / R / 4, 128);   // 2 x-halves, 8 strip-groups, 128 planes = 2048 CTAs
    dim3 block(32, 4);                // 4 warps, each owns one 256x16 strip
    conv5x5_kernel<<<grid, block>>>(X, Kw, Out);
}